// round 16
// baseline (speedup 1.0000x reference)
#include <cuda_runtime.h>
#include <math.h>

#define BB 512
#define NN 120
#define DD 64
#define ROWS (BB*NN)           // 61440
#define NBINS 32

typedef unsigned long long u64;

// ---------------- scratch (static device arrays; no cudaMalloc) ----------------
__device__ float  g_q[ROWS*DD];
__device__ float  g_k[ROWS*DD];
__device__ float  g_v[ROWS*DD];
__device__ float  g_gam[ROWS];
__device__ float  g_o[ROWS*DD];
// packed twiddles: twp[d2*32+f] = (cos(w*f*2d2), cos(w*f*(2d2+1)), sin(...), sin(...))
__device__ float4 g_twp[1024];
// W repacked over e-pairs: P[e2*32+lane] = (W[2e2][2l], W[2e2+1][2l], W[2e2][2l+1], W[2e2+1][2l+1])
__device__ float4 g_Wqp[1024], g_Wkp[1024], g_Wvp[1024], g_Wop[1024];

// ---------------- f32x2 helpers ----------------
__device__ __forceinline__ u64 fma2(u64 a, u64 b, u64 c) {
    u64 d; asm("fma.rn.f32x2 %0,%1,%2,%3;" : "=l"(d) : "l"(a), "l"(b), "l"(c)); return d;
}
__device__ __forceinline__ u64 mul2(u64 a, u64 b) {
    u64 d; asm("mul.rn.f32x2 %0,%1,%2;" : "=l"(d) : "l"(a), "l"(b)); return d;
}
__device__ __forceinline__ u64 dup2(float v) {
    u64 r; asm("mov.b64 %0,{%1,%1};" : "=l"(r) : "f"(v)); return r;
}
__device__ __forceinline__ float2 unp(u64 v) {
    float a, b; asm("mov.b64 {%0,%1},%2;" : "=f"(a), "=f"(b) : "l"(v));
    return make_float2(a, b);
}
// S' = clip(g*S + delta*k, +-10)
__device__ __forceinline__ u64 upd2(u64 S, u64 k, u64 g, u64 delta) {
    u64 r;
    asm("{\n\t"
        ".reg .f32 lo,hi;\n\t"
        ".reg .b64 t;\n\t"
        "mul.rn.f32x2 t, %2, %3;\n\t"
        "fma.rn.f32x2 t, %4, %1, t;\n\t"
        "mov.b64 {lo,hi}, t;\n\t"
        "min.f32 lo, lo, 0f41200000;\n\t"
        "max.f32 lo, lo, 0fC1200000;\n\t"
        "min.f32 hi, hi, 0f41200000;\n\t"
        "max.f32 hi, hi, 0fC1200000;\n\t"
        "mov.b64 %0, {lo,hi};\n\t"
        "}"
        : "=l"(r) : "l"(S), "l"(k), "l"(delta), "l"(g));
    return r;
}

// ---------------- init: packed twiddles + W e-pair repack ----------------
__global__ void init_kernel(const float* __restrict__ Wq, const float* __restrict__ Wk,
                            const float* __restrict__ Wv, const float* __restrict__ Wo) {
    int i = blockIdx.x * blockDim.x + threadIdx.x;
    if (i < 1024) {
        int d2 = i >> 5, f = i & 31;
        int m0 = (f * (2*d2))     & 63;       // exact modular angle reduction
        int m1 = (f * (2*d2 + 1)) & 63;
        const double w = 2.0 * 3.14159265358979323846 / 64.0;
        g_twp[i] = make_float4((float)cos(w*m0), (float)cos(w*m1),
                               (float)sin(w*m0), (float)sin(w*m1));
    } else if (i < 5120) {
        int s = (i - 1024) >> 10, j = (i - 1024) & 1023;
        int e2 = j >> 5, l = j & 31;
        const float* W = (s == 0) ? Wq : (s == 1) ? Wk : (s == 2) ? Wv : Wo;
        float4*      P = (s == 0) ? g_Wqp : (s == 1) ? g_Wkp : (s == 2) ? g_Wvp : g_Wop;
        int a = (2*e2)*DD + 2*l;
        P[j] = make_float4(W[a], W[a+DD], W[a+1], W[a+DD+1]);
    }
}

// matvec pass over one packed matrix: 8 rows, accumulators aE/aO (even/odd e partials)
#define MATVEC_PASS(Wp, aE, aO)                                            \
    {                                                                       \
        _Pragma("unroll")                                                   \
        for (int r = 0; r < 8; r++) { aE[r] = 0ull; aO[r] = 0ull; }        \
        _Pragma("unroll 2")                                                 \
        for (int e4 = 0; e4 < 16; e4++) {                                   \
            ulonglong2 w0 = Wp[(2*e4)*32 + lane];                           \
            ulonglong2 w1 = Wp[(2*e4+1)*32 + lane];                         \
            _Pragma("unroll")                                               \
            for (int r = 0; r < 8; r++) {                                   \
                ulonglong2 hh = ((const ulonglong2*)sh[warp][r])[e4];       \
                aE[r] = fma2(hh.x, w0.x, aE[r]);                            \
                aO[r] = fma2(hh.x, w0.y, aO[r]);                            \
                aE[r] = fma2(hh.y, w1.x, aE[r]);                            \
                aO[r] = fma2(hh.y, w1.y, aO[r]);                            \
            }                                                               \
        }                                                                   \
    }

// ---------------- preprocess: 8 rows/warp, separate passes ----------------
__global__ void __launch_bounds__(256) pre_kernel(
    const float* __restrict__ x,  const float* __restrict__ g_norm,
    const float* __restrict__ bv,
    const float* __restrict__ W1, const float* __restrict__ b1,
    const float* __restrict__ W2, const float* __restrict__ b2)
{
    const int warp = threadIdx.x >> 5;
    const int lane = threadIdx.x & 31;
    const int row0 = blockIdx.x * 64 + warp * 8;
    __shared__ __align__(16) float sh[8][8][DD];
    __shared__ float smag[8][8][NBINS];

    // ---- zc_rms for 8 rows (variance identity; parallel reductions) ----
    float2 gv = ((const float2*)g_norm)[lane];
    #pragma unroll
    for (int r = 0; r < 8; r++) {
        float2 xv = ((const float2*)(x + (row0 + r)*DD))[lane];
        float s  = xv.x + xv.y;
        float ss = xv.x*xv.x + xv.y*xv.y;
        #pragma unroll
        for (int o = 16; o; o >>= 1) {
            s  += __shfl_xor_sync(0xffffffffu, s,  o);
            ss += __shfl_xor_sync(0xffffffffu, ss, o);
        }
        float mean = s * (1.0f/64.0f);
        float var  = fmaf(-mean, mean, ss * (1.0f/64.0f));
        float rn = rsqrtf(var + 1e-8f);
        sh[warp][r][2*lane]   = (xv.x - mean) * rn * gv.x;
        sh[warp][r][2*lane+1] = (xv.y - mean) * rn * gv.y;
    }
    __syncwarp();

    u64 aE[8], aO[8];

    // ---- Q pass ----
    MATVEC_PASS(((const ulonglong2*)g_Wqp), aE, aO)
    #pragma unroll
    for (int r = 0; r < 8; r++) {
        float2 e0 = unp(aE[r]), e1 = unp(aO[r]);
        float q0 = e0.x + e0.y, q1 = e1.x + e1.y;
        float qs = q0*q0 + q1*q1;
        #pragma unroll
        for (int o = 16; o; o >>= 1) qs += __shfl_xor_sync(0xffffffffu, qs, o);
        float qr = rsqrtf(qs + 1e-8f);
        ((float2*)(g_q + (row0 + r)*DD))[lane] = make_float2(q0*qr, q1*qr);
    }

    // ---- K pass ----
    MATVEC_PASS(((const ulonglong2*)g_Wkp), aE, aO)
    #pragma unroll
    for (int r = 0; r < 8; r++) {
        float2 e0 = unp(aE[r]), e1 = unp(aO[r]);
        float k0 = e0.x + e0.y, k1 = e1.x + e1.y;
        float ks = k0*k0 + k1*k1;
        #pragma unroll
        for (int o = 16; o; o >>= 1) ks += __shfl_xor_sync(0xffffffffu, ks, o);
        float kr = rsqrtf(ks + 1e-8f);
        ((float2*)(g_k + (row0 + r)*DD))[lane] = make_float2(k0*kr, k1*kr);
    }

    // ---- V pass ----
    MATVEC_PASS(((const ulonglong2*)g_Wvp), aE, aO)
    {
        float2 bvv = ((const float2*)bv)[lane];
        #pragma unroll
        for (int r = 0; r < 8; r++) {
            float2 e0 = unp(aE[r]), e1 = unp(aO[r]);
            ((float2*)(g_v + (row0 + r)*DD))[lane] =
                make_float2(e0.x + e0.y + bvv.x, e1.x + e1.y + bvv.y);
        }
    }

    // ---- DFT pass: bin = lane, packed twiddles ----
    {
        u64 re2[8], im2[8];
        #pragma unroll
        for (int r = 0; r < 8; r++) { re2[r] = 0ull; im2[r] = 0ull; }
        const ulonglong2* Twp = (const ulonglong2*)g_twp;
        #pragma unroll 2
        for (int d4 = 0; d4 < 16; d4++) {
            ulonglong2 t0 = Twp[(2*d4)*32 + lane];     // (cos pair, sin pair)
            ulonglong2 t1 = Twp[(2*d4+1)*32 + lane];
            #pragma unroll
            for (int r = 0; r < 8; r++) {
                ulonglong2 hh = ((const ulonglong2*)sh[warp][r])[d4];
                re2[r] = fma2(hh.x, t0.x, re2[r]);
                im2[r] = fma2(hh.x, t0.y, im2[r]);
                re2[r] = fma2(hh.y, t1.x, re2[r]);
                im2[r] = fma2(hh.y, t1.y, im2[r]);
            }
        }
        #pragma unroll
        for (int r = 0; r < 8; r++) {
            float2 rr = unp(re2[r]), ii = unp(im2[r]);
            float re = rr.x + rr.y, im = ii.x + ii.y;
            smag[warp][r][lane] = sqrtf(re*re + im*im);
        }
    }
    __syncwarp();

    // ---- gate: 8 lanes per row, two half-passes of 4 rows ----
    #pragma unroll
    for (int half = 0; half < 8; half += 4) {
        int r   = half + (lane >> 3);
        int bnd = lane & 7;
        const float* mg = smag[warp][r];
        float en = 0.25f * (mg[4*bnd] + mg[4*bnd+1] + mg[4*bnd+2] + mg[4*bnd+3]);
        float esum = en;
        esum += __shfl_xor_sync(0xffffffffu, esum, 1);
        esum += __shfl_xor_sync(0xffffffffu, esum, 2);
        esum += __shfl_xor_sync(0xffffffffu, esum, 4);
        float eni = en / fmaxf(esum, 1e-8f);
        float z0 = b1[2*bnd], z1 = b1[2*bnd+1];
        int gbase = lane & 24;
        #pragma unroll
        for (int i = 0; i < 8; i++) {
            float ei = __shfl_sync(0xffffffffu, eni, gbase + i);
            z0 = fmaf(ei, W1[i*16 + 2*bnd],     z0);
            z1 = fmaf(ei, W1[i*16 + 2*bnd + 1], z1);
        }
        float s0 = z0 / (1.0f + expf(-z0)) * W2[2*bnd];
        float s1 = z1 / (1.0f + expf(-z1)) * W2[2*bnd+1];
        float hid = s0 + s1;
        hid += __shfl_xor_sync(0xffffffffu, hid, 1);
        hid += __shfl_xor_sync(0xffffffffu, hid, 2);
        hid += __shfl_xor_sync(0xffffffffu, hid, 4);
        if (bnd == 0) {
            float z2 = hid + b2[0];
            g_gam[row0 + r] = 0.5f + 0.49f / (1.0f + expf(-z2));
        }
    }
}

// ---------------- scan: 2 CTAs per batch, 64 threads each (16 row-groups x 4 cg) ----------------
// thread (rg, cg): rows {base+2rg, base+2rg+1}, interleaved cols {chunk*16 + cg*4 + j}.
// Rows are independent across CTAs (k/q/v/gam shared per batch); splitting the batch
// over 2 CTAs fixes the 512-on-148 load imbalance (15% -> ~1%).
__global__ void __launch_bounds__(64, 12) scan_kernel() {
    const int b    = blockIdx.x >> 1;
    const int half = blockIdx.x & 1;       // row half: [0,32) or [32,64)
    const int cg   = threadIdx.x & 3;      // col-group (stride-4 interleave)
    const int rg   = threadIdx.x >> 2;     // row-group 0..15

    const ulonglong2* __restrict__ kp = (const ulonglong2*)(g_k + b*NN*DD + cg*4);
    const ulonglong2* __restrict__ qp = (const ulonglong2*)(g_q + b*NN*DD + cg*4);
    const float2* __restrict__ vp = (const float2*)(g_v + b*NN*DD) + half*16 + rg;
    const float*  __restrict__ gp = g_gam + b*NN;
    float2*       __restrict__ op = (float2*)(g_o + b*NN*DD) + half*16 + rg;

    u64 S0[8], S1[8];                      // 2 rows, 16 interleaved cols each
    #pragma unroll
    for (int i = 0; i < 8; i++) { S0[i] = 0ull; S1[i] = 0ull; }

    #pragma unroll 1
    for (int t = 0; t < NN; t++) {
        ulonglong2 kA = kp[0], kB = kp[4], kC = kp[8], kD = kp[12];
        ulonglong2 qA = qp[0], qB = qp[4], qC = qp[8], qD = qp[12];
        kp += 16; qp += 16;
        float gc  = *gp++;
        float2 vc = *vp; vp += 32;

        u64 k2[8] = {kA.x, kA.y, kB.x, kB.y, kC.x, kC.y, kD.x, kD.y};
        u64 q2[8] = {qA.x, qA.y, qB.x, qB.y, qC.x, qC.y, qD.x, qD.y};

        // pred per row: two 4-u64 chains, reduce over col-groups
        u64 pa0 = mul2(S0[0], k2[0]);
        pa0 = fma2(S0[1], k2[1], pa0);
        pa0 = fma2(S0[2], k2[2], pa0);
        pa0 = fma2(S0[3], k2[3], pa0);
        u64 pb0 = mul2(S0[4], k2[4]);
        pb0 = fma2(S0[5], k2[5], pb0);
        pb0 = fma2(S0[6], k2[6], pb0);
        pb0 = fma2(S0[7], k2[7], pb0);
        u64 pa1 = mul2(S1[0], k2[0]);
        pa1 = fma2(S1[1], k2[1], pa1);
        pa1 = fma2(S1[2], k2[2], pa1);
        pa1 = fma2(S1[3], k2[3], pa1);
        u64 pb1 = mul2(S1[4], k2[4]);
        pb1 = fma2(S1[5], k2[5], pb1);
        pb1 = fma2(S1[6], k2[6], pb1);
        pb1 = fma2(S1[7], k2[7], pb1);
        float2 ua0 = unp(pa0), ub0 = unp(pb0);
        float2 ua1 = unp(pa1), ub1 = unp(pb1);
        float pred0 = (ua0.x + ua0.y) + (ub0.x + ub0.y);
        float pred1 = (ua1.x + ua1.y) + (ub1.x + ub1.y);
        pred0 += __shfl_xor_sync(0xffffffffu, pred0, 1);
        pred1 += __shfl_xor_sync(0xffffffffu, pred1, 1);
        pred0 += __shfl_xor_sync(0xffffffffu, pred0, 2);
        pred1 += __shfl_xor_sync(0xffffffffu, pred1, 2);

        float d0 = fminf(fmaxf(vc.x - pred0, -5.0f), 5.0f);
        float d1 = fminf(fmaxf(vc.y - pred1, -5.0f), 5.0f);
        u64 g2  = dup2(gc);
        u64 dl0 = dup2(d0);
        u64 dl1 = dup2(d1);

        // update + o for both rows (packed)
        u64 oa0, ob0, oa1, ob1;
        S0[0] = upd2(S0[0], k2[0], g2, dl0);  oa0 = mul2(S0[0], q2[0]);
        S1[0] = upd2(S1[0], k2[0], g2, dl1);  oa1 = mul2(S1[0], q2[0]);
        S0[1] = upd2(S0[1], k2[1], g2, dl0);  oa0 = fma2(S0[1], q2[1], oa0);
        S1[1] = upd2(S1[1], k2[1], g2, dl1);  oa1 = fma2(S1[1], q2[1], oa1);
        S0[2] = upd2(S0[2], k2[2], g2, dl0);  oa0 = fma2(S0[2], q2[2], oa0);
        S1[2] = upd2(S1[2], k2[2], g2, dl1);  oa1 = fma2(S1[2], q2[2], oa1);
        S0[3] = upd2(S0[3], k2[3], g2, dl0);  oa0 = fma2(S0[3], q2[3], oa0);
        S1[3] = upd2(S1[3], k2[3], g2, dl1);  oa1 = fma2(S1[3], q2[3], oa1);
        S0[4] = upd2(S0[4], k2[4], g2, dl0);  ob0 = mul2(S0[4], q2[4]);
        S1[4] = upd2(S1[4], k2[4], g2, dl1);  ob1 = mul2(S1[4], q2[4]);
        S0[5] = upd2(S0[5], k2[5], g2, dl0);  ob0 = fma2(S0[5], q2[5], ob0);
        S1[5] = upd2(S1[5], k2[5], g2, dl1);  ob1 = fma2(S1[5], q2[5], ob1);
        S0[6] = upd2(S0[6], k2[6], g2, dl0);  ob0 = fma2(S0[6], q2[6], ob0);
        S1[6] = upd2(S1[6], k2[6], g2, dl1);  ob1 = fma2(S1[6], q2[6], ob1);
        S0[7] = upd2(S0[7], k2[7], g2, dl0);  ob0 = fma2(S0[7], q2[7], ob0);
        S1[7] = upd2(S1[7], k2[7], g2, dl1);  ob1 = fma2(S1[7], q2[7], ob1);

        float2 oa02 = unp(oa0), ob02 = unp(ob0);
        float2 oa12 = unp(oa1), ob12 = unp(ob1);
        float o0 = (oa02.x + oa02.y) + (ob02.x + ob02.y);
        float o1 = (oa12.x + oa12.y) + (ob12.x + ob12.y);
        o0 += __shfl_xor_sync(0xffffffffu, o0, 1);
        o1 += __shfl_xor_sync(0xffffffffu, o1, 1);
        o0 += __shfl_xor_sync(0xffffffffu, o0, 2);
        o1 += __shfl_xor_sync(0xffffffffu, o1, 2);
        if (cg == 0) op[t*32] = make_float2(o0, o1);
    }
}

// ---------------- epilogue: 8 rows/warp ----------------
__global__ void __launch_bounds__(256) post_kernel(
    const float* __restrict__ x, const float* __restrict__ g_post,
    const float* __restrict__ bo, float* __restrict__ out)
{
    const int warp = threadIdx.x >> 5;
    const int lane = threadIdx.x & 31;
    const int row0 = blockIdx.x * 64 + warp * 8;
    __shared__ __align__(16) float sh[8][8][DD];

    float2 gp2 = ((const float2*)g_post)[lane];
    #pragma unroll
    for (int r = 0; r < 8; r++) {
        float2 ov = ((const float2*)(g_o + (row0 + r)*DD))[lane];
        float s  = ov.x + ov.y;
        float ss = ov.x*ov.x + ov.y*ov.y;
        #pragma unroll
        for (int o = 16; o; o >>= 1) {
            s  += __shfl_xor_sync(0xffffffffu, s,  o);
            ss += __shfl_xor_sync(0xffffffffu, ss, o);
        }
        float mean = s * (1.0f/64.0f);
        float var  = fmaf(-mean, mean, ss * (1.0f/64.0f));
        float rn = rsqrtf(var + 1e-8f);
        sh[warp][r][2*lane]   = (ov.x - mean) * rn * gp2.x;
        sh[warp][r][2*lane+1] = (ov.y - mean) * rn * gp2.y;
    }
    __syncwarp();

    u64 aE[8], aO[8];
    MATVEC_PASS(((const ulonglong2*)g_Wop), aE, aO)

    float2 bov = ((const float2*)bo)[lane];
    #pragma unroll
    for (int r = 0; r < 8; r++) {
        float2 e0 = unp(aE[r]), e1 = unp(aO[r]);
        int row = row0 + r;
        float2 xv = ((const float2*)(x + row*DD))[lane];
        ((float2*)(out + row*DD))[lane] =
            make_float2(xv.x + e0.x + e0.y + bov.x,
                        xv.y + e1.x + e1.y + bov.y);
    }
}

// ---------------- launch ----------------
extern "C" void kernel_launch(void* const* d_in, const int* in_sizes, int n_in,
                              void* d_out, int out_size)
{
    const float* x      = (const float*)d_in[0];
    const float* g_norm = (const float*)d_in[1];
    const float* Wq     = (const float*)d_in[2];
    const float* Wk     = (const float*)d_in[3];
    const float* Wv     = (const float*)d_in[4];
    const float* bv     = (const float*)d_in[5];
    const float* Wo     = (const float*)d_in[6];
    const float* bo     = (const float*)d_in[7];
    const float* g_post = (const float*)d_in[8];
    const float* W1     = (const float*)d_in[9];
    const float* b1     = (const float*)d_in[10];
    const float* W2     = (const float*)d_in[11];
    const float* b2     = (const float*)d_in[12];
    float* out          = (float*)d_out;

    init_kernel<<<20, 256>>>(Wq, Wk, Wv, Wo);
    pre_kernel<<<ROWS/64, 256>>>(x, g_norm, bv, W1, b1, W2, b2);
    scan_kernel<<<BB*2, 64>>>();
    post_kernel<<<ROWS/64, 256>>>(x, g_post, bo, out);
}

// round 17
// speedup vs baseline: 1.1290x; 1.1290x over previous
#include <cuda_runtime.h>
#include <math.h>

#define BB 512
#define NN 120
#define DD 64
#define ROWS (BB*NN)           // 61440
#define NBINS 32

typedef unsigned long long u64;

// ---------------- scratch (static device arrays; no cudaMalloc) ----------------
__device__ float  g_q[ROWS*DD];
__device__ float  g_k[ROWS*DD];
__device__ float  g_v[ROWS*DD];
__device__ float  g_gam[ROWS];
__device__ float  g_o[ROWS*DD];
// packed twiddles: twp[d2*32+f] = (cos(w*f*2d2), cos(w*f*(2d2+1)), sin(...), sin(...))
__device__ float4 g_twp[1024];
// W repacked over e-pairs: P[e2*32+lane] = (W[2e2][2l], W[2e2+1][2l], W[2e2][2l+1], W[2e2+1][2l+1])
__device__ float4 g_Wqp[1024], g_Wkp[1024], g_Wvp[1024], g_Wop[1024];

// ---------------- f32x2 helpers ----------------
__device__ __forceinline__ u64 fma2(u64 a, u64 b, u64 c) {
    u64 d; asm("fma.rn.f32x2 %0,%1,%2,%3;" : "=l"(d) : "l"(a), "l"(b), "l"(c)); return d;
}
__device__ __forceinline__ u64 mul2(u64 a, u64 b) {
    u64 d; asm("mul.rn.f32x2 %0,%1,%2;" : "=l"(d) : "l"(a), "l"(b)); return d;
}
__device__ __forceinline__ u64 dup2(float v) {
    u64 r; asm("mov.b64 %0,{%1,%1};" : "=l"(r) : "f"(v)); return r;
}
__device__ __forceinline__ float2 unp(u64 v) {
    float a, b; asm("mov.b64 {%0,%1},%2;" : "=f"(a), "=f"(b) : "l"(v));
    return make_float2(a, b);
}
// S' = clip(g*S + delta*k, +-10)
__device__ __forceinline__ u64 upd2(u64 S, u64 k, u64 g, u64 delta) {
    u64 r;
    asm("{\n\t"
        ".reg .f32 lo,hi;\n\t"
        ".reg .b64 t;\n\t"
        "mul.rn.f32x2 t, %2, %3;\n\t"
        "fma.rn.f32x2 t, %4, %1, t;\n\t"
        "mov.b64 {lo,hi}, t;\n\t"
        "min.f32 lo, lo, 0f41200000;\n\t"
        "max.f32 lo, lo, 0fC1200000;\n\t"
        "min.f32 hi, hi, 0f41200000;\n\t"
        "max.f32 hi, hi, 0fC1200000;\n\t"
        "mov.b64 %0, {lo,hi};\n\t"
        "}"
        : "=l"(r) : "l"(S), "l"(k), "l"(delta), "l"(g));
    return r;
}

// ---------------- init: packed twiddles + W e-pair repack ----------------
__global__ void init_kernel(const float* __restrict__ Wq, const float* __restrict__ Wk,
                            const float* __restrict__ Wv, const float* __restrict__ Wo) {
    int i = blockIdx.x * blockDim.x + threadIdx.x;
    if (i < 1024) {
        int d2 = i >> 5, f = i & 31;
        int m0 = (f * (2*d2))     & 63;       // exact modular angle reduction
        int m1 = (f * (2*d2 + 1)) & 63;
        const double w = 2.0 * 3.14159265358979323846 / 64.0;
        g_twp[i] = make_float4((float)cos(w*m0), (float)cos(w*m1),
                               (float)sin(w*m0), (float)sin(w*m1));
    } else if (i < 5120) {
        int s = (i - 1024) >> 10, j = (i - 1024) & 1023;
        int e2 = j >> 5, l = j & 31;
        const float* W = (s == 0) ? Wq : (s == 1) ? Wk : (s == 2) ? Wv : Wo;
        float4*      P = (s == 0) ? g_Wqp : (s == 1) ? g_Wkp : (s == 2) ? g_Wvp : g_Wop;
        int a = (2*e2)*DD + 2*l;
        P[j] = make_float4(W[a], W[a+DD], W[a+1], W[a+DD+1]);
    }
}

// 4-row matvec pass over one packed matrix (8 u64 accumulators live)
#define MATVEC_PASS4(Wp, aE, aO)                                            \
    {                                                                       \
        _Pragma("unroll")                                                   \
        for (int r = 0; r < 4; r++) { aE[r] = 0ull; aO[r] = 0ull; }         \
        _Pragma("unroll 4")                                                 \
        for (int e2 = 0; e2 < 32; e2++) {                                   \
            ulonglong2 w = Wp[e2*32 + lane];                                \
            _Pragma("unroll")                                               \
            for (int r = 0; r < 4; r++) {                                   \
                u64 h2 = ((const u64*)sh[warp][r])[e2];                     \
                aE[r] = fma2(h2, w.x, aE[r]);                               \
                aO[r] = fma2(h2, w.y, aO[r]);                               \
            }                                                               \
        }                                                                   \
    }

// ---------------- preprocess: 4 rows/warp, SEPARATE passes (low reg pressure) ----------------
__global__ void __launch_bounds__(256, 4) pre_kernel(
    const float* __restrict__ x,  const float* __restrict__ g_norm,
    const float* __restrict__ bv,
    const float* __restrict__ W1, const float* __restrict__ b1,
    const float* __restrict__ W2, const float* __restrict__ b2)
{
    const int warp = threadIdx.x >> 5;
    const int lane = threadIdx.x & 31;
    const int row0 = blockIdx.x * 32 + warp * 4;
    __shared__ __align__(16) float sh[8][4][DD];
    __shared__ float smag[8][4][NBINS];

    // ---- zc_rms for 4 rows (variance identity; parallel reductions) ----
    float2 gv = ((const float2*)g_norm)[lane];
    #pragma unroll
    for (int r = 0; r < 4; r++) {
        float2 xv = ((const float2*)(x + (row0 + r)*DD))[lane];
        float s  = xv.x + xv.y;
        float ss = xv.x*xv.x + xv.y*xv.y;
        #pragma unroll
        for (int o = 16; o; o >>= 1) {
            s  += __shfl_xor_sync(0xffffffffu, s,  o);
            ss += __shfl_xor_sync(0xffffffffu, ss, o);
        }
        float mean = s * (1.0f/64.0f);
        float var  = fmaf(-mean, mean, ss * (1.0f/64.0f));
        float rn = rsqrtf(var + 1e-8f);
        sh[warp][r][2*lane]   = (xv.x - mean) * rn * gv.x;
        sh[warp][r][2*lane+1] = (xv.y - mean) * rn * gv.y;
    }
    __syncwarp();

    u64 aE[4], aO[4];

    // ---- Q pass ----
    MATVEC_PASS4(((const ulonglong2*)g_Wqp), aE, aO)
    #pragma unroll
    for (int r = 0; r < 4; r++) {
        float2 e0 = unp(aE[r]), e1 = unp(aO[r]);
        float q0 = e0.x + e0.y, q1 = e1.x + e1.y;
        float qs = q0*q0 + q1*q1;
        #pragma unroll
        for (int o = 16; o; o >>= 1) qs += __shfl_xor_sync(0xffffffffu, qs, o);
        float qr = rsqrtf(qs + 1e-8f);
        ((float2*)(g_q + (row0 + r)*DD))[lane] = make_float2(q0*qr, q1*qr);
    }

    // ---- K pass ----
    MATVEC_PASS4(((const ulonglong2*)g_Wkp), aE, aO)
    #pragma unroll
    for (int r = 0; r < 4; r++) {
        float2 e0 = unp(aE[r]), e1 = unp(aO[r]);
        float k0 = e0.x + e0.y, k1 = e1.x + e1.y;
        float ks = k0*k0 + k1*k1;
        #pragma unroll
        for (int o = 16; o; o >>= 1) ks += __shfl_xor_sync(0xffffffffu, ks, o);
        float kr = rsqrtf(ks + 1e-8f);
        ((float2*)(g_k + (row0 + r)*DD))[lane] = make_float2(k0*kr, k1*kr);
    }

    // ---- V pass ----
    MATVEC_PASS4(((const ulonglong2*)g_Wvp), aE, aO)
    {
        float2 bvv = ((const float2*)bv)[lane];
        #pragma unroll
        for (int r = 0; r < 4; r++) {
            float2 e0 = unp(aE[r]), e1 = unp(aO[r]);
            ((float2*)(g_v + (row0 + r)*DD))[lane] =
                make_float2(e0.x + e0.y + bvv.x, e1.x + e1.y + bvv.y);
        }
    }

    // ---- DFT pass: bin = lane, packed twiddles ----
    {
        u64 re2[4] = {0,0,0,0}, im2[4] = {0,0,0,0};
        const ulonglong2* Twp = (const ulonglong2*)g_twp;
        #pragma unroll 4
        for (int d2 = 0; d2 < 32; d2++) {
            ulonglong2 t2 = Twp[d2*32 + lane];    // (cos pair, sin pair)
            #pragma unroll
            for (int r = 0; r < 4; r++) {
                u64 h2 = ((const u64*)sh[warp][r])[d2];
                re2[r] = fma2(h2, t2.x, re2[r]);
                im2[r] = fma2(h2, t2.y, im2[r]);
            }
        }
        #pragma unroll
        for (int r = 0; r < 4; r++) {
            float2 rr = unp(re2[r]), ii = unp(im2[r]);
            float re = rr.x + rr.y, im = ii.x + ii.y;
            smag[warp][r][lane] = sqrtf(re*re + im*im);
        }
    }
    __syncwarp();

    // ---- gate: 8 lanes per row, lane = (row, band) ----
    {
        int r   = lane >> 3;      // row within group of 4
        int bnd = lane & 7;       // band index
        const float* mg = smag[warp][r];
        float en = 0.25f * (mg[4*bnd] + mg[4*bnd+1] + mg[4*bnd+2] + mg[4*bnd+3]);
        float esum = en;
        esum += __shfl_xor_sync(0xffffffffu, esum, 1);
        esum += __shfl_xor_sync(0xffffffffu, esum, 2);
        esum += __shfl_xor_sync(0xffffffffu, esum, 4);
        float eni = en / fmaxf(esum, 1e-8f);
        float z0 = b1[2*bnd], z1 = b1[2*bnd+1];
        int gbase = lane & 24;    // start lane of this 8-lane group
        #pragma unroll
        for (int i = 0; i < 8; i++) {
            float ei = __shfl_sync(0xffffffffu, eni, gbase + i);
            z0 = fmaf(ei, W1[i*16 + 2*bnd],     z0);
            z1 = fmaf(ei, W1[i*16 + 2*bnd + 1], z1);
        }
        float s0 = z0 / (1.0f + expf(-z0)) * W2[2*bnd];
        float s1 = z1 / (1.0f + expf(-z1)) * W2[2*bnd+1];
        float hid = s0 + s1;
        hid += __shfl_xor_sync(0xffffffffu, hid, 1);
        hid += __shfl_xor_sync(0xffffffffu, hid, 2);
        hid += __shfl_xor_sync(0xffffffffu, hid, 4);
        if (bnd == 0) {
            float z2 = hid + b2[0];
            g_gam[row0 + r] = 0.5f + 0.49f / (1.0f + expf(-z2));
        }
    }
}

// ---------------- scan: 2 rows x 16 INTERLEAVED cols per thread (R15 best) ----------------
// thread (rg, cg): rows {2rg, 2rg+1}, cols {chunk*16 + cg*4 + j : chunk 0..3, j 0..3}.
__global__ void __launch_bounds__(128, 4) scan_kernel() {
    const int b  = blockIdx.x;
    const int cg = threadIdx.x & 3;        // col-group (stride-4 interleave)
    const int rg = threadIdx.x >> 2;       // row-group 0..31 (rows 2rg, 2rg+1)

    // base at cg*4 floats; chunks at +16 floats (= +4 ulonglong2)
    const ulonglong2* __restrict__ kp = (const ulonglong2*)(g_k + b*NN*DD + cg*4);
    const ulonglong2* __restrict__ qp = (const ulonglong2*)(g_q + b*NN*DD + cg*4);
    const float2* __restrict__ vp = (const float2*)(g_v + b*NN*DD) + rg;
    const float*  __restrict__ gp = g_gam + b*NN;
    float2*       __restrict__ op = (float2*)(g_o + b*NN*DD) + rg;

    u64 S0[8], S1[8];                      // rows 2rg and 2rg+1, 16 interleaved cols
    #pragma unroll
    for (int i = 0; i < 8; i++) { S0[i] = 0ull; S1[i] = 0ull; }

    #pragma unroll 1
    for (int t = 0; t < NN; t++) {
        ulonglong2 kA = kp[0], kB = kp[4], kC = kp[8], kD = kp[12];
        ulonglong2 qA = qp[0], qB = qp[4], qC = qp[8], qD = qp[12];
        kp += 16; qp += 16;
        float gc  = *gp++;
        float2 vc = *vp; vp += 32;

        u64 k2[8] = {kA.x, kA.y, kB.x, kB.y, kC.x, kC.y, kD.x, kD.y};
        u64 q2[8] = {qA.x, qA.y, qB.x, qB.y, qC.x, qC.y, qD.x, qD.y};

        // pred per row: two 4-u64 chains, reduce over col-groups
        u64 pa0 = mul2(S0[0], k2[0]);
        pa0 = fma2(S0[1], k2[1], pa0);
        pa0 = fma2(S0[2], k2[2], pa0);
        pa0 = fma2(S0[3], k2[3], pa0);
        u64 pb0 = mul2(S0[4], k2[4]);
        pb0 = fma2(S0[5], k2[5], pb0);
        pb0 = fma2(S0[6], k2[6], pb0);
        pb0 = fma2(S0[7], k2[7], pb0);
        u64 pa1 = mul2(S1[0], k2[0]);
        pa1 = fma2(S1[1], k2[1], pa1);
        pa1 = fma2(S1[2], k2[2], pa1);
        pa1 = fma2(S1[3], k2[3], pa1);
        u64 pb1 = mul2(S1[4], k2[4]);
        pb1 = fma2(S1[5], k2[5], pb1);
        pb1 = fma2(S1[6], k2[6], pb1);
        pb1 = fma2(S1[7], k2[7], pb1);
        float2 ua0 = unp(pa0), ub0 = unp(pb0);
        float2 ua1 = unp(pa1), ub1 = unp(pb1);
        float pred0 = (ua0.x + ua0.y) + (ub0.x + ub0.y);
        float pred1 = (ua1.x + ua1.y) + (ub1.x + ub1.y);
        pred0 += __shfl_xor_sync(0xffffffffu, pred0, 1);
        pred1 += __shfl_xor_sync(0xffffffffu, pred1, 1);
        pred0 += __shfl_xor_sync(0xffffffffu, pred0, 2);
        pred1 += __shfl_xor_sync(0xffffffffu, pred1, 2);

        float d0 = fminf(fmaxf(vc.x - pred0, -5.0f), 5.0f);
        float d1 = fminf(fmaxf(vc.y - pred1, -5.0f), 5.0f);
        u64 g2  = dup2(gc);
        u64 dl0 = dup2(d0);
        u64 dl1 = dup2(d1);

        // update + o for both rows (packed)
        u64 oa0, ob0, oa1, ob1;
        S0[0] = upd2(S0[0], k2[0], g2, dl0);  oa0 = mul2(S0[0], q2[0]);
        S1[0] = upd2(S1[0], k2[0], g2, dl1);  oa1 = mul2(S1[0], q2[0]);
        S0[1] = upd2(S0[1], k2[1], g2, dl0);  oa0 = fma2(S0[1], q2[1], oa0);
        S1[1] = upd2(S1[1], k2[1], g2, dl1);  oa1 = fma2(S1[1], q2[1], oa1);
        S0[2] = upd2(S0[2], k2[2], g2, dl0);  oa0 = fma2(S0[2], q2[2], oa0);
        S1[2] = upd2(S1[2], k2[2], g2, dl1);  oa1 = fma2(S1[2], q2[2], oa1);
        S0[3] = upd2(S0[3], k2[3], g2, dl0);  oa0 = fma2(S0[3], q2[3], oa0);
        S1[3] = upd2(S1[3], k2[3], g2, dl1);  oa1 = fma2(S1[3], q2[3], oa1);
        S0[4] = upd2(S0[4], k2[4], g2, dl0);  ob0 = mul2(S0[4], q2[4]);
        S1[4] = upd2(S1[4], k2[4], g2, dl1);  ob1 = mul2(S1[4], q2[4]);
        S0[5] = upd2(S0[5], k2[5], g2, dl0);  ob0 = fma2(S0[5], q2[5], ob0);
        S1[5] = upd2(S1[5], k2[5], g2, dl1);  ob1 = fma2(S1[5], q2[5], ob1);
        S0[6] = upd2(S0[6], k2[6], g2, dl0);  ob0 = fma2(S0[6], q2[6], ob0);
        S1[6] = upd2(S1[6], k2[6], g2, dl1);  ob1 = fma2(S1[6], q2[6], ob1);
        S0[7] = upd2(S0[7], k2[7], g2, dl0);  ob0 = fma2(S0[7], q2[7], ob0);
        S1[7] = upd2(S1[7], k2[7], g2, dl1);  ob1 = fma2(S1[7], q2[7], ob1);

        float2 oa02 = unp(oa0), ob02 = unp(ob0);
        float2 oa12 = unp(oa1), ob12 = unp(ob1);
        float o0 = (oa02.x + oa02.y) + (ob02.x + ob02.y);
        float o1 = (oa12.x + oa12.y) + (ob12.x + ob12.y);
        o0 += __shfl_xor_sync(0xffffffffu, o0, 1);
        o1 += __shfl_xor_sync(0xffffffffu, o1, 1);
        o0 += __shfl_xor_sync(0xffffffffu, o0, 2);
        o1 += __shfl_xor_sync(0xffffffffu, o1, 2);
        if (cg == 0) op[t*32] = make_float2(o0, o1);
    }
}

// ---------------- epilogue: 4 rows/warp (R15) + occupancy floor 5 ----------------
__global__ void __launch_bounds__(256, 5) post_kernel(
    const float* __restrict__ x, const float* __restrict__ g_post,
    const float* __restrict__ bo, float* __restrict__ out)
{
    const int warp = threadIdx.x >> 5;
    const int lane = threadIdx.x & 31;
    const int row0 = blockIdx.x * 32 + warp * 4;
    __shared__ __align__(16) float sh[8][4][DD];

    float2 gp2 = ((const float2*)g_post)[lane];
    #pragma unroll
    for (int r = 0; r < 4; r++) {
        float2 ov = ((const float2*)(g_o + (row0 + r)*DD))[lane];
        float s  = ov.x + ov.y;
        float ss = ov.x*ov.x + ov.y*ov.y;
        #pragma unroll
        for (int o = 16; o; o >>= 1) {
            s  += __shfl_xor_sync(0xffffffffu, s,  o);
            ss += __shfl_xor_sync(0xffffffffu, ss, o);
        }
        float mean = s * (1.0f/64.0f);
        float var  = fmaf(-mean, mean, ss * (1.0f/64.0f));
        float rn = rsqrtf(var + 1e-8f);
        sh[warp][r][2*lane]   = (ov.x - mean) * rn * gp2.x;
        sh[warp][r][2*lane+1] = (ov.y - mean) * rn * gp2.y;
    }
    __syncwarp();

    u64 aE[4], aO[4];
    MATVEC_PASS4(((const ulonglong2*)g_Wop), aE, aO)

    float2 bov = ((const float2*)bo)[lane];
    #pragma unroll
    for (int r = 0; r < 4; r++) {
        float2 e0 = unp(aE[r]), e1 = unp(aO[r]);
        int row = row0 + r;
        float2 xv = ((const float2*)(x + row*DD))[lane];
        ((float2*)(out + row*DD))[lane] =
            make_float2(xv.x + e0.x + e0.y + bov.x,
                        xv.y + e1.x + e1.y + bov.y);
    }
}

// ---------------- launch ----------------
extern "C" void kernel_launch(void* const* d_in, const int* in_sizes, int n_in,
                              void* d_out, int out_size)
{
    const float* x      = (const float*)d_in[0];
    const float* g_norm = (const float*)d_in[1];
    const float* Wq     = (const float*)d_in[2];
    const float* Wk     = (const float*)d_in[3];
    const float* Wv     = (const float*)d_in[4];
    const float* bv     = (const float*)d_in[5];
    const float* Wo     = (const float*)d_in[6];
    const float* bo     = (const float*)d_in[7];
    const float* g_post = (const float*)d_in[8];
    const float* W1     = (const float*)d_in[9];
    const float* b1     = (const float*)d_in[10];
    const float* W2     = (const float*)d_in[11];
    const float* b2     = (const float*)d_in[12];
    float* out          = (float*)d_out;

    init_kernel<<<20, 256>>>(Wq, Wk, Wv, Wo);
    pre_kernel<<<ROWS/32, 256>>>(x, g_norm, bv, W1, b1, W2, b2);
    scan_kernel<<<BB, 128>>>();
    post_kernel<<<ROWS/32, 256>>>(x, g_post, bo, out);
}